// round 3
// baseline (speedup 1.0000x reference)
#include <cuda_runtime.h>
#include <cstdint>

#define BINS 10
#define C 16
#define MAX_BLOCKS 2048
#define THREADS 256

// Allocation-free scratch: per-block, per-bin partials. Fully overwritten
// every run by pass1 (no zeroing kernel needed).
__device__ float    g_part_sum[BINS * MAX_BLOCKS];
__device__ unsigned g_part_cnt[BINS * MAX_BLOCKS];

__global__ __launch_bounds__(THREADS) void ghm_pass1_kernel(
    const float* __restrict__ x,
    const int* __restrict__ tgt,   // int32 targets in {0,1}
    int N)
{
    float    lsum[BINS];
    unsigned lcnt[BINS];
#pragma unroll
    for (int b = 0; b < BINS; b++) { lsum[b] = 0.0f; lcnt[b] = 0u; }

    const int stride = gridDim.x * blockDim.x;
    for (int row = blockIdx.x * blockDim.x + threadIdx.x; row < N; row += stride) {
        const float4* p = reinterpret_cast<const float4*>(x + (size_t)row * C);
        float4 a  = p[0];
        float4 b4 = p[1];
        float4 c4 = p[2];
        float4 d4 = p[3];

        float v[C] = {a.x, a.y, a.z, a.w,
                      b4.x, b4.y, b4.z, b4.w,
                      c4.x, c4.y, c4.z, c4.w,
                      d4.x, d4.y, d4.z, d4.w};

        int t = tgt[row];
        t = min(max(t, 0), C - 1);        // crash-proof clamp

        // row max (tree) + select xt = v[t]
        float m = v[0];
#pragma unroll
        for (int i = 1; i < C; i++) m = fmaxf(m, v[i]);

        float xt = v[0];
#pragma unroll
        for (int i = 1; i < C; i++) xt = (i == t) ? v[i] : xt;

        // s = sum exp(v - m), and pick out e_t = exp(xt - m) on the fly
        float s = 0.0f;
        float et = 0.0f;
#pragma unroll
        for (int i = 0; i < C; i++) {
            float e = __expf(v[i] - m);
            s += e;
            et = (i == t) ? e : et;
        }

        float nll = m + __logf(s) - xt;        // -log_softmax[t]
        float pt  = __fdividef(et, s);         // softmax[t]
        float g   = fabsf(pt - (float)t);      // gradient norm

        // bin = searchsorted(arange(11)/10, g, 'right') - 1, clipped to 9
        int bin = 0;
#pragma unroll
        for (int j = 1; j <= BINS; j++) bin += (g >= (float)j / 10.0f) ? 1 : 0;
        if (bin > BINS - 1) bin = BINS - 1;

        lsum[bin] += nll;
        lcnt[bin] += 1u;
    }

    // ---- block reduction: warp shuffle -> shared -> one plain store/bin ----
    __shared__ float    s_sum[BINS];
    __shared__ unsigned s_cnt[BINS];
    if (threadIdx.x < BINS) { s_sum[threadIdx.x] = 0.0f; s_cnt[threadIdx.x] = 0u; }
    __syncthreads();

#pragma unroll
    for (int b = 0; b < BINS; b++) {
        float    vs = lsum[b];
        unsigned vc = lcnt[b];
#pragma unroll
        for (int off = 16; off > 0; off >>= 1) {
            vs += __shfl_down_sync(0xFFFFFFFFu, vs, off);
            vc += __shfl_down_sync(0xFFFFFFFFu, vc, off);
        }
        if ((threadIdx.x & 31) == 0) {
            atomicAdd(&s_sum[b], vs);
            atomicAdd(&s_cnt[b], vc);
        }
    }
    __syncthreads();

    if (threadIdx.x < BINS) {
        g_part_sum[threadIdx.x * MAX_BLOCKS + blockIdx.x] = s_sum[threadIdx.x];
        g_part_cnt[threadIdx.x * MAX_BLOCKS + blockIdx.x] = s_cnt[threadIdx.x];
    }
}

// One block, 10 warps: warp b reduces bin b over nblocks partials (coalesced).
__global__ __launch_bounds__(320) void ghm_finalize_kernel(float* out, int N, int nblocks) {
    int w   = threadIdx.x >> 5;   // bin
    int lid = threadIdx.x & 31;

    __shared__ double s_term[BINS];

    double ds = 0.0;
    unsigned long long dc = 0ULL;
    for (int blk = lid; blk < nblocks; blk += 32) {
        ds += (double)g_part_sum[w * MAX_BLOCKS + blk];
        dc += (unsigned long long)g_part_cnt[w * MAX_BLOCKS + blk];
    }
#pragma unroll
    for (int off = 16; off > 0; off >>= 1) {
        ds += __shfl_down_sync(0xFFFFFFFFu, ds, off);
        dc += __shfl_down_sync(0xFFFFFFFFu, dc, off);
    }
    if (lid == 0) {
        double c = (double)dc;
        if (c < 1.0) c = 1.0;
        s_term[w] = ((double)N / (double)BINS) / c * ds;
    }
    __syncthreads();

    if (threadIdx.x == 0) {
        double total = 0.0;
#pragma unroll
        for (int b = 0; b < BINS; b++) total += s_term[b];
        out[0] = (float)total;
    }
}

extern "C" void kernel_launch(void* const* d_in, const int* in_sizes, int n_in,
                              void* d_out, int out_size)
{
    // Robust input-order detection: inputs has C=16x more elements than target.
    int i_x = 0, i_t = 1;
    if (n_in >= 2 && in_sizes[1] > in_sizes[0]) { i_x = 1; i_t = 0; }

    const float* x   = (const float*)d_in[i_x];
    const int*   tgt = (const int*)d_in[i_t];
    float*       out = (float*)d_out;

    int N = in_sizes[i_t];
    (void)out_size;

    int blocks = MAX_BLOCKS;
    int maxb = (N + THREADS - 1) / THREADS;
    if (blocks > maxb) blocks = maxb;

    ghm_pass1_kernel<<<blocks, THREADS>>>(x, tgt, N);
    ghm_finalize_kernel<<<1, 320>>>(out, N, blocks);
}

// round 4
// speedup vs baseline: 1.1667x; 1.1667x over previous
#include <cuda_runtime.h>
#include <cstdint>

#define BINS 10
#define C 16
#define MAX_BLOCKS 1184   // 8 * 148 SMs
#define THREADS 256

// Allocation-free scratch: per-block, per-bin partials (fully overwritten
// every run by pass1) + per-bin terms from stage-2 reduce.
__device__ float    g_part_sum[BINS * MAX_BLOCKS];
__device__ unsigned g_part_cnt[BINS * MAX_BLOCKS];
__device__ double   g_term[BINS];

__global__ __launch_bounds__(THREADS) void ghm_pass1_kernel(
    const float* __restrict__ x,
    const int* __restrict__ tgt,   // int32 targets in {0,1}
    int N)
{
    float    lsum[BINS];
    unsigned lcnt[BINS];
#pragma unroll
    for (int b = 0; b < BINS; b++) { lsum[b] = 0.0f; lcnt[b] = 0u; }

    const int stride = gridDim.x * blockDim.x;
    for (int row = blockIdx.x * blockDim.x + threadIdx.x; row < N; row += stride) {
        const float4* p = reinterpret_cast<const float4*>(x + (size_t)row * C);
        float4 a  = __ldcs(p + 0);
        float4 b4 = __ldcs(p + 1);
        float4 c4 = __ldcs(p + 2);
        float4 d4 = __ldcs(p + 3);
        int t = __ldcs(tgt + row);
        t = min(max(t, 0), 1);            // targets are {0,1}; crash-proof

        float v[C] = {a.x, a.y, a.z, a.w,
                      b4.x, b4.y, b4.z, b4.w,
                      c4.x, c4.y, c4.z, c4.w,
                      d4.x, d4.y, d4.z, d4.w};

        // row max
        float m = v[0];
#pragma unroll
        for (int i = 1; i < C; i++) m = fmaxf(m, v[i]);

        float xt = t ? v[1] : v[0];

        // s = sum exp(v - m); pick e_t on the fly (t < 2)
        float s = 0.0f;
        float et = 0.0f;
#pragma unroll
        for (int i = 0; i < C; i++) {
            float e = __expf(v[i] - m);
            s += e;
            if (i < 2) et = (i == t) ? e : et;
        }

        float nll = m + __logf(s) - xt;        // -log_softmax[t]
        float pt  = __fdividef(et, s);         // softmax[t]
        float g   = fabsf(pt - (float)t);      // gradient norm

        // bin = searchsorted(arange(11)/10, g, 'right') - 1, clipped to 9
        int bin = 0;
#pragma unroll
        for (int j = 1; j <= BINS; j++) bin += (g >= (float)j / 10.0f) ? 1 : 0;
        if (bin > BINS - 1) bin = BINS - 1;

        lsum[bin] += nll;
        lcnt[bin] += 1u;
    }

    // ---- block reduction: warp shuffle -> shared -> one plain store/bin ----
    __shared__ float    s_sum[BINS];
    __shared__ unsigned s_cnt[BINS];
    if (threadIdx.x < BINS) { s_sum[threadIdx.x] = 0.0f; s_cnt[threadIdx.x] = 0u; }
    __syncthreads();

#pragma unroll
    for (int b = 0; b < BINS; b++) {
        float    vs = lsum[b];
        unsigned vc = lcnt[b];
#pragma unroll
        for (int off = 16; off > 0; off >>= 1) {
            vs += __shfl_down_sync(0xFFFFFFFFu, vs, off);
            vc += __shfl_down_sync(0xFFFFFFFFu, vc, off);
        }
        if ((threadIdx.x & 31) == 0) {
            atomicAdd(&s_sum[b], vs);
            atomicAdd(&s_cnt[b], vc);
        }
    }
    __syncthreads();

    if (threadIdx.x < BINS) {
        g_part_sum[threadIdx.x * MAX_BLOCKS + blockIdx.x] = s_sum[threadIdx.x];
        g_part_cnt[threadIdx.x * MAX_BLOCKS + blockIdx.x] = s_cnt[threadIdx.x];
    }
}

// Stage 2: one block per bin, 256 threads, parallel coalesced reduce.
__global__ __launch_bounds__(256) void ghm_reduce_kernel(int N, int nblocks) {
    int bin = blockIdx.x;
    int tid = threadIdx.x;

    float sum = 0.0f;
    unsigned cnt = 0u;
    for (int blk = tid; blk < nblocks; blk += 256) {
        sum += g_part_sum[bin * MAX_BLOCKS + blk];
        cnt += g_part_cnt[bin * MAX_BLOCKS + blk];
    }

    __shared__ float    sh_s[256];
    __shared__ unsigned sh_c[256];
    sh_s[tid] = sum; sh_c[tid] = cnt;
    __syncthreads();
#pragma unroll
    for (int off = 128; off >= 32; off >>= 1) {
        if (tid < off) { sh_s[tid] += sh_s[tid + off]; sh_c[tid] += sh_c[tid + off]; }
        __syncthreads();
    }
    if (tid < 32) {
        float    vs = sh_s[tid];
        unsigned vc = sh_c[tid];
#pragma unroll
        for (int off = 16; off > 0; off >>= 1) {
            vs += __shfl_down_sync(0xFFFFFFFFu, vs, off);
            vc += __shfl_down_sync(0xFFFFFFFFu, vc, off);
        }
        if (tid == 0) {
            double c = (double)vc;
            if (c < 1.0) c = 1.0;
            g_term[bin] = ((double)N / (double)BINS) / c * (double)vs;
        }
    }
}

// Stage 3: sum the 10 per-bin terms.
__global__ void ghm_final_sum_kernel(float* out) {
    if (threadIdx.x == 0) {
        double total = 0.0;
#pragma unroll
        for (int b = 0; b < BINS; b++) total += g_term[b];
        out[0] = (float)total;
    }
}

extern "C" void kernel_launch(void* const* d_in, const int* in_sizes, int n_in,
                              void* d_out, int out_size)
{
    // Robust input-order detection: inputs has C=16x more elements than target.
    int i_x = 0, i_t = 1;
    if (n_in >= 2 && in_sizes[1] > in_sizes[0]) { i_x = 1; i_t = 0; }

    const float* x   = (const float*)d_in[i_x];
    const int*   tgt = (const int*)d_in[i_t];
    float*       out = (float*)d_out;

    int N = in_sizes[i_t];
    (void)out_size;

    int blocks = MAX_BLOCKS;
    int maxb = (N + THREADS - 1) / THREADS;
    if (blocks > maxb) blocks = maxb;

    ghm_pass1_kernel<<<blocks, THREADS>>>(x, tgt, N);
    ghm_reduce_kernel<<<BINS, 256>>>(N, blocks);
    ghm_final_sum_kernel<<<1, 32>>>(out);
}